// round 14
// baseline (speedup 1.0000x reference)
#include <cuda_runtime.h>
#include <cuda_bf16.h>
#include <math.h>
#include <stdint.h>

#define BB 2
#define TT 2048
#define CC 768
#define HH 12
#define DD 64
#define NLEFT 6
#define NQKV (3 * CC)   // 2304
#define MM (BB * TT)    // 4096

// Scratch. q,k: [which][b][h][t][d].  v: [b][h][d][t] (transposed!)
__device__ float g_qkv[3ull * BB * HH * TT * DD];
__device__ float g_ctx[(size_t)BB * TT * CC];
__device__ float g_xr[(size_t)MM * CC];
__device__ float g_wqkv[(size_t)NQKV * CC];
__device__ float g_wo[(size_t)CC * CC];

// ---------------------------------------------------------------------------
// helpers
// ---------------------------------------------------------------------------
__device__ __forceinline__ float tf32r(float f) {
    uint32_t u;
    asm("cvt.rna.tf32.f32 %0, %1;" : "=r"(u) : "f"(f));
    return __uint_as_float(u);
}
__device__ __forceinline__ float ex2(float x) {
    float y;
    asm("ex2.approx.ftz.f32 %0, %1;" : "=f"(y) : "f"(x));
    return y;
}
__device__ __forceinline__ void mma_tf32(float* c, const uint32_t* a, const uint32_t* b) {
    asm("mma.sync.aligned.m16n8k8.row.col.f32.tf32.tf32.f32 "
        "{%0,%1,%2,%3}, {%4,%5,%6,%7}, {%8,%9}, {%0,%1,%2,%3};"
        : "+f"(c[0]), "+f"(c[1]), "+f"(c[2]), "+f"(c[3])
        : "r"(a[0]), "r"(a[1]), "r"(a[2]), "r"(a[3]), "r"(b[0]), "r"(b[1]));
}
__device__ __forceinline__ void ldsm4(uint32_t* r, uint32_t saddr) {
    asm volatile("ldmatrix.sync.aligned.m8n8.x4.shared.b16 {%0,%1,%2,%3}, [%4];"
                 : "=r"(r[0]), "=r"(r[1]), "=r"(r[2]), "=r"(r[3]) : "r"(saddr));
}
__device__ __forceinline__ void cpa16(uint32_t dst, const void* src) {
    asm volatile("cp.async.ca.shared.global [%0], [%1], 16;" :: "r"(dst), "l"(src));
}
#define CP_COMMIT asm volatile("cp.async.commit_group;")
#define CP_WAIT0  asm volatile("cp.async.wait_group 0;")
#define CP_WAIT1  asm volatile("cp.async.wait_group 1;")

// ---------------------------------------------------------------------------
// pre-round: out[i] = tf32(in[i])
// ---------------------------------------------------------------------------
__global__ void round_kernel(const float4* __restrict__ in, float4* __restrict__ out,
                             int n4)
{
    int i = blockIdx.x * blockDim.x + threadIdx.x;
    if (i < n4) {
        float4 v = in[i];
        v.x = tf32r(v.x); v.y = tf32r(v.y); v.z = tf32r(v.z); v.w = tf32r(v.w);
        out[i] = v;
    }
}

// ---------------------------------------------------------------------------
// TF32 GEMM NT, 3-stage cp.async pipeline, 1 sync per k-iter.
// MODE 0: plain store. MODE 1: tf32-rounded scatter to g_qkv (v transposed).
// ---------------------------------------------------------------------------
#define ASZ (128 * 36)          // floats per stage per operand

template <int MODE>
__global__ __launch_bounds__(256)
void gemm_tf32(const float* __restrict__ A, const float* __restrict__ Bw,
               const float* __restrict__ bias, float* __restrict__ Cout,
               int M, int N, int K)
{
    extern __shared__ float sm[];
    float* As = sm;             // 3 stages
    float* Bs = sm + 3 * ASZ;   // 3 stages

    const int bm = blockIdx.y * 128;
    const int bn = blockIdx.x * 128;
    const int tid = threadIdx.x;
    const int lane = tid & 31;
    const int warp = tid >> 5;
    const int wm = (warp >> 2) * 64;
    const int wn = (warp & 3) * 32;

    float acc[4][4][4] = {};

    const int lrow = tid >> 3;          // 0..31
    const int lcol = (tid & 7) * 4;     // 0..28

    const uint32_t uA = (uint32_t)__cvta_generic_to_shared(As);
    const uint32_t uB = (uint32_t)__cvta_generic_to_shared(Bs);
    const uint32_t aA = uA + (((wm + (lane & 15)) * 36 + (lane >> 4) * 4) << 2);
    const uint32_t aB = uB + (((wn + (lane & 7) + ((lane >> 4) << 3)) * 36
                               + ((lane >> 3) & 1) * 4) << 2);
    const uint32_t dA = uA + ((lrow * 36 + lcol) << 2);
    const uint32_t dB = uB + ((lrow * 36 + lcol) << 2);

    const int nk = K / 32;

    auto issue = [&](int i, int st) {
        const int k1 = i * 32;
        const uint32_t so = (uint32_t)(st * ASZ * 4);
#pragma unroll
        for (int p = 0; p < 4; p++) {
            cpa16(dA + so + p * (32 * 36 * 4),
                  &A[(size_t)(bm + lrow + p * 32) * K + k1 + lcol]);
            cpa16(dB + so + p * (32 * 36 * 4),
                  &Bw[(size_t)(bn + lrow + p * 32) * K + k1 + lcol]);
        }
    };

    issue(0, 0); CP_COMMIT;
    issue(1, 1); CP_COMMIT;

    for (int i = 0; i < nk; i++) {
        CP_WAIT1;              // stage i%3 ready (≤1 younger group pending)
        __syncthreads();       // also: all threads done computing stage (i-1)%3
        if (i + 2 < nk) issue(i + 2, (i + 2) % 3);
        CP_COMMIT;             // always commit (keeps group counting exact)

        const uint32_t co = (uint32_t)((i % 3) * ASZ * 4);
#pragma unroll
        for (int ks = 0; ks < 4; ks++) {
            uint32_t af[4][4];
#pragma unroll
            for (int mi = 0; mi < 4; mi++)
                ldsm4(af[mi], aA + co + mi * (16 * 36 * 4) + ks * 32);
#pragma unroll
            for (int njp = 0; njp < 2; njp++) {
                uint32_t b4[4];
                ldsm4(b4, aB + co + njp * (16 * 36 * 4) + ks * 32);
#pragma unroll
                for (int mi = 0; mi < 4; mi++) {
                    mma_tf32(acc[mi][2 * njp + 0], af[mi], b4);
                    mma_tf32(acc[mi][2 * njp + 1], af[mi], b4 + 2);
                }
            }
        }
    }

    // epilogue
#pragma unroll
    for (int mi = 0; mi < 4; mi++) {
        const int r0 = bm + wm + mi * 16 + (lane >> 2);
#pragma unroll
        for (int nj = 0; nj < 4; nj++) {
            const int c = bn + wn + nj * 8 + 2 * (lane & 3);
            const float b0 = bias[c], b1 = bias[c + 1];
            float v00 = acc[mi][nj][0] + b0, v01 = acc[mi][nj][1] + b1;
            float v10 = acc[mi][nj][2] + b0, v11 = acc[mi][nj][3] + b1;
            if (MODE == 0) {
                *(float2*)&Cout[(size_t)r0 * N + c] = make_float2(v00, v01);
                *(float2*)&Cout[(size_t)(r0 + 8) * N + c] = make_float2(v10, v11);
            } else {
                v00 = tf32r(v00); v01 = tf32r(v01);
                v10 = tf32r(v10); v11 = tf32r(v11);
#pragma unroll
                for (int e = 0; e < 2; e++) {
                    const int n = c + e;
                    const int which = n / CC;
                    const int rem = n - which * CC;
                    const int hh = rem >> 6;
                    const int dd = rem & 63;
#pragma unroll
                    for (int rr = 0; rr < 2; rr++) {
                        const int m = r0 + rr * 8;
                        const int bb = m / TT;
                        const int t = m - bb * TT;
                        size_t off;
                        if (which == 2)   // V transposed: [b][h][d][t]
                            off = 2ull * BB * HH * TT * DD
                                + (((size_t)bb * HH + hh) * DD + dd) * TT + t;
                        else
                            off = ((((size_t)which * BB + bb) * HH + hh) * TT + t) * DD + dd;
                        g_qkv[off] = (rr == 0) ? (e == 0 ? v00 : v01)
                                               : (e == 0 ? v10 : v11);
                    }
                }
            }
        }
    }
}

// ---------------------------------------------------------------------------
// TF32 mma flash attention, 2-stage cp.async K/V pipeline, V pre-transposed.
// Block: 128 threads (4 warps), one (b,h) x 64-row q tile. Bc = 64.
// smem floats: Qs[64*68] | Ks[2][64*68] | Vt[2][64*68] | mask[2][64]
// ---------------------------------------------------------------------------
#define QST 68
#define KST 68
#define QS_OFF 0
#define KS_OFF (64 * QST)                   // 4352
#define VS_OFF (KS_OFF + 2 * 64 * KST)      // 13056
#define MK_OFF (VS_OFF + 2 * 64 * KST)      // 21760
#define SC_LOG2 0.18033688011112042f        // 0.125 * log2(e)
#define ATTN_SMEM ((MK_OFF + 2 * 64) * 4)

__global__ __launch_bounds__(128)
void attn_tf32(const int* __restrict__ amask, float* __restrict__ ctx)
{
    extern __shared__ float smf[];
    float* Qs = smf + QS_OFF;
    int* mks = (int*)(smf + MK_OFF);

    const int qb = blockIdx.x;
    const int bh = blockIdx.y;
    const int b = bh / HH, h = bh % HH;
    const bool causal = (h < NLEFT);
    const int tid = threadIdx.x, lane = tid & 31, warp = tid >> 5;

    const float* Qp = g_qkv + ((size_t)b * HH + h) * (size_t)TT * DD;
    const float* Kp = g_qkv + (size_t)BB * HH * TT * DD
                    + ((size_t)b * HH + h) * (size_t)TT * DD;
    const float* Vp = g_qkv + 2ull * BB * HH * TT * DD
                    + ((size_t)b * HH + h) * (size_t)DD * TT;   // [d][t]
    const int q0 = qb * 64;

    const uint32_t uS = (uint32_t)__cvta_generic_to_shared(smf);
    const uint32_t aQ = uS + (((warp * 16 + (lane & 15)) * QST + (lane >> 4) * 4) << 2);
    const uint32_t lpat = (((lane & 7) + ((lane >> 4) << 3)) * KST
                           + ((lane >> 3) & 1) * 4) << 2;
    const uint32_t aK = uS + (KS_OFF << 2) + lpat;
    const uint32_t aV = uS + (VS_OFF << 2) + lpat;
    // cp.async destinations
    const int clin_row = tid >> 4;             // 0..7
    const int clin_f4 = (tid & 15) * 4;
    const uint32_t dK = uS + (KS_OFF << 2) + ((clin_row * KST + clin_f4) << 2);
    const uint32_t dV = uS + (VS_OFF << 2) + ((clin_row * KST + clin_f4) << 2);
    const uint32_t dM = uS + (MK_OFF << 2) + (tid << 4);

    const int ktb = causal ? 0 : qb;
    const int kte = causal ? (qb + 1) : (TT / 64);

    auto issue = [&](int kt, int s) {
        const uint32_t so = (uint32_t)(s * 64 * KST * 4);
#pragma unroll
        for (int u = 0; u < 8; u++) {
            const int row = clin_row + u * 8;
            cpa16(dK + so + u * (8 * KST * 4),
                  &Kp[(size_t)(kt * 64 + row) * DD + clin_f4]);
            cpa16(dV + so + u * (8 * KST * 4),
                  &Vp[(size_t)row * TT + kt * 64 + clin_f4]);    // Vt rows = d
        }
        if (tid < 16) cpa16(dM + s * 256, &amask[b * TT + kt * 64 + tid * 4]);
        CP_COMMIT;
    };

    issue(ktb, 0);

    // stage Q tile (scale by 0.125*log2e, round) — overlaps stage-0 cp.async
#pragma unroll
    for (int u = 0; u < 8; u++) {
        const int linear = u * 128 + tid;
        const int row = linear >> 4, f4 = (linear & 15) * 4;
        float4 v = *(const float4*)&Qp[(size_t)(q0 + row) * DD + f4];
        float* d = &Qs[row * QST + f4];
        d[0] = tf32r(v.x * SC_LOG2); d[1] = tf32r(v.y * SC_LOG2);
        d[2] = tf32r(v.z * SC_LOG2); d[3] = tf32r(v.w * SC_LOG2);
    }
    __syncthreads();

    uint32_t qa[8][4];
#pragma unroll
    for (int kf = 0; kf < 8; kf++) ldsm4(qa[kf], aQ + kf * 32);

    float oc[8][4] = {};
    float m0 = -1e30f, m1 = -1e30f, l0 = 0.f, l1 = 0.f;
    const int qrA = q0 + warp * 16 + (lane >> 2);
    const int qrB = qrA + 8;
    const int rps = warp * 16 + (lane >> 2);

    for (int kt = ktb; kt < kte; kt++) {
        const int s = (kt - ktb) & 1;
        CP_WAIT0;
        __syncthreads();       // stage s ready; all threads done with stage s^1
        if (kt + 1 < kte) issue(kt + 1, s ^ 1);

        const int* mk = mks + s * 64;
        const int mv0l = mk[lane], mv1l = mk[lane + 32];
        const bool allv = __all_sync(0xffffffffu, (mv0l != 0) && (mv1l != 0));
        const uint32_t co = (uint32_t)(s * 64 * KST * 4);

        // S = Q K^T (log2 units)
        float sc[8][4] = {};
#pragma unroll
        for (int njp = 0; njp < 4; njp++) {
#pragma unroll
            for (int kf = 0; kf < 8; kf++) {
                uint32_t b4[4];
                ldsm4(b4, aK + co + njp * (16 * KST * 4) + kf * 32);
                mma_tf32(sc[2 * njp + 0], qa[kf], b4);
                mma_tf32(sc[2 * njp + 1], qa[kf], b4 + 2);
            }
        }

        // mask + row max
        const bool diag = (kt == qb);
        float tmax0 = -1e30f, tmax1 = -1e30f;
        if (allv && !diag) {
#pragma unroll
            for (int nj = 0; nj < 8; nj++) {
                tmax0 = fmaxf(tmax0, fmaxf(sc[nj][0], sc[nj][1]));
                tmax1 = fmaxf(tmax1, fmaxf(sc[nj][2], sc[nj][3]));
            }
        } else {
#pragma unroll
            for (int nj = 0; nj < 8; nj++) {
                const int kl = nj * 8 + 2 * (lane & 3);
                const int key = kt * 64 + kl;
                const int mv0 = mk[kl], mv1 = mk[kl + 1];
                float s0 = sc[nj][0], s1 = sc[nj][1];
                float s2 = sc[nj][2], s3 = sc[nj][3];
                bool bd0A = (mv0 == 0), bd1A = (mv1 == 0);
                bool bd0B = bd0A, bd1B = bd1A;
                if (diag) {
                    if (causal) {
                        bd0A |= (key > qrA); bd1A |= (key + 1 > qrA);
                        bd0B |= (key > qrB); bd1B |= (key + 1 > qrB);
                    } else {
                        bd0A |= (key < qrA); bd1A |= (key + 1 < qrA);
                        bd0B |= (key < qrB); bd1B |= (key + 1 < qrB);
                    }
                }
                s0 = bd0A ? -1e30f : s0; s1 = bd1A ? -1e30f : s1;
                s2 = bd0B ? -1e30f : s2; s3 = bd1B ? -1e30f : s3;
                sc[nj][0] = s0; sc[nj][1] = s1; sc[nj][2] = s2; sc[nj][3] = s3;
                tmax0 = fmaxf(tmax0, fmaxf(s0, s1));
                tmax1 = fmaxf(tmax1, fmaxf(s2, s3));
            }
        }
        tmax0 = fmaxf(tmax0, __shfl_xor_sync(0xffffffffu, tmax0, 1));
        tmax0 = fmaxf(tmax0, __shfl_xor_sync(0xffffffffu, tmax0, 2));
        tmax1 = fmaxf(tmax1, __shfl_xor_sync(0xffffffffu, tmax1, 1));
        tmax1 = fmaxf(tmax1, __shfl_xor_sync(0xffffffffu, tmax1, 2));

        const float mn0 = fmaxf(m0, tmax0), mn1 = fmaxf(m1, tmax1);
        const float cr0 = ex2(m0 - mn0), cr1 = ex2(m1 - mn1);
        m0 = mn0; m1 = mn1;
        l0 *= cr0; l1 *= cr1;
#pragma unroll
        for (int nj = 0; nj < 8; nj++) {
            oc[nj][0] *= cr0; oc[nj][1] *= cr0;
            oc[nj][2] *= cr1; oc[nj][3] *= cr1;
        }

        // P = 2^(S - m) -> Qs (warp-private rows)
#pragma unroll
        for (int nj = 0; nj < 8; nj++) {
            const int kl = nj * 8 + 2 * (lane & 3);
            float p0 = ex2(sc[nj][0] - mn0), p1 = ex2(sc[nj][1] - mn0);
            float p2 = ex2(sc[nj][2] - mn1), p3 = ex2(sc[nj][3] - mn1);
            l0 += p0 + p1; l1 += p2 + p3;
            *(float2*)&Qs[rps * QST + kl] = make_float2(tf32r(p0), tf32r(p1));
            *(float2*)&Qs[(rps + 8) * QST + kl] = make_float2(tf32r(p2), tf32r(p3));
        }
        __syncwarp();

        // O += P V  (V fragments via ldmatrix on transposed tile)
#pragma unroll
        for (int kf = 0; kf < 8; kf++) {
            uint32_t pa[4];
            ldsm4(pa, aQ + kf * 32);
#pragma unroll
            for (int njp = 0; njp < 4; njp++) {
                uint32_t b4[4];
                ldsm4(b4, aV + co + njp * (16 * KST * 4) + kf * 32);
                mma_tf32(oc[2 * njp + 0], pa, b4);
                mma_tf32(oc[2 * njp + 1], pa, b4 + 2);
            }
        }
    }

    l0 += __shfl_xor_sync(0xffffffffu, l0, 1);
    l0 += __shfl_xor_sync(0xffffffffu, l0, 2);
    l1 += __shfl_xor_sync(0xffffffffu, l1, 1);
    l1 += __shfl_xor_sync(0xffffffffu, l1, 2);
    const float i0 = 1.f / l0, i1 = 1.f / l1;

#pragma unroll
    for (int nj = 0; nj < 8; nj++) {
        const int d = nj * 8 + 2 * (lane & 3);
        *(float2*)&ctx[((size_t)b * TT + qrA) * CC + h * DD + d] =
            make_float2(tf32r(oc[nj][0] * i0), tf32r(oc[nj][1] * i0));
        *(float2*)&ctx[((size_t)b * TT + qrB) * CC + h * DD + d] =
            make_float2(tf32r(oc[nj][2] * i1), tf32r(oc[nj][3] * i1));
    }
}

// ---------------------------------------------------------------------------
extern "C" void kernel_launch(void* const* d_in, const int* in_sizes, int n_in,
                              void* d_out, int out_size)
{
    const float* x      = (const float*)d_in[0];
    const int*   amask  = (const int*)d_in[1];
    const float* Wqkv_w = (const float*)d_in[2];
    const float* Wqkv_b = (const float*)d_in[3];
    const float* Wo_w   = (const float*)d_in[4];
    const float* Wo_b   = (const float*)d_in[5];
    float* out = (float*)d_out;

    float *d_ctx, *d_xr, *d_wqkv, *d_wo;
    cudaGetSymbolAddress((void**)&d_ctx, g_ctx);
    cudaGetSymbolAddress((void**)&d_xr, g_xr);
    cudaGetSymbolAddress((void**)&d_wqkv, g_wqkv);
    cudaGetSymbolAddress((void**)&d_wo, g_wo);

    const int GEMM_SMEM = 6 * ASZ * 4;   // 110592 B (3 stages x 2 operands)
    cudaFuncSetAttribute(gemm_tf32<0>, cudaFuncAttributeMaxDynamicSharedMemorySize,
                         GEMM_SMEM);
    cudaFuncSetAttribute(gemm_tf32<1>, cudaFuncAttributeMaxDynamicSharedMemorySize,
                         GEMM_SMEM);
    cudaFuncSetAttribute(attn_tf32, cudaFuncAttributeMaxDynamicSharedMemorySize,
                         ATTN_SMEM);

    // 0) pre-round x / Wqkv / Wo to tf32
    {
        const int n1 = MM * CC / 4, n2 = NQKV * CC / 4, n3 = CC * CC / 4;
        round_kernel<<<(n1 + 255) / 256, 256>>>((const float4*)x, (float4*)d_xr, n1);
        round_kernel<<<(n2 + 255) / 256, 256>>>((const float4*)Wqkv_w, (float4*)d_wqkv, n2);
        round_kernel<<<(n3 + 255) / 256, 256>>>((const float4*)Wo_w, (float4*)d_wo, n3);
    }
    // 1) QKV projection -> g_qkv (tf32-rounded, v transposed)
    {
        dim3 grid(NQKV / 128, MM / 128);   // (18, 32)
        gemm_tf32<1><<<grid, 256, GEMM_SMEM>>>(d_xr, d_wqkv, Wqkv_b, nullptr,
                                               MM, NQKV, CC);
    }
    // 2) attention -> g_ctx (tf32-rounded)
    {
        dim3 grid(TT / 64, BB * HH);       // (32, 24)
        attn_tf32<<<grid, 128, ATTN_SMEM>>>(amask, d_ctx);
    }
    // 3) output projection -> out (fp32)
    {
        dim3 grid(CC / 128, MM / 128);     // (6, 32)
        gemm_tf32<0><<<grid, 256, GEMM_SMEM>>>(d_ctx, d_wo, Wo_b, out, MM, CC, CC);
    }
}

// round 16
// speedup vs baseline: 1.0657x; 1.0657x over previous
#include <cuda_runtime.h>
#include <cuda_bf16.h>
#include <math.h>
#include <stdint.h>

#define BB 2
#define TT 2048
#define CC 768
#define HH 12
#define DD 64
#define NLEFT 6
#define NQKV (3 * CC)   // 2304
#define MM (BB * TT)    // 4096

// Scratch: qkv in [which][b][h][t][d], ctx in [B][T][C]
__device__ float g_qkv[3ull * BB * HH * TT * DD];
__device__ float g_ctx[(size_t)BB * TT * CC];
__device__ float g_xr[(size_t)MM * CC];
__device__ float g_wqkv[(size_t)NQKV * CC];
__device__ float g_wo[(size_t)CC * CC];

// ---------------------------------------------------------------------------
// helpers
// ---------------------------------------------------------------------------
__device__ __forceinline__ float tf32r(float f) {
    uint32_t u;
    asm("cvt.rna.tf32.f32 %0, %1;" : "=r"(u) : "f"(f));
    return __uint_as_float(u);
}
__device__ __forceinline__ float ex2(float x) {
    float y;
    asm("ex2.approx.ftz.f32 %0, %1;" : "=f"(y) : "f"(x));
    return y;
}
__device__ __forceinline__ void mma_tf32(float* c, const uint32_t* a, const uint32_t* b) {
    asm("mma.sync.aligned.m16n8k8.row.col.f32.tf32.tf32.f32 "
        "{%0,%1,%2,%3}, {%4,%5,%6,%7}, {%8,%9}, {%0,%1,%2,%3};"
        : "+f"(c[0]), "+f"(c[1]), "+f"(c[2]), "+f"(c[3])
        : "r"(a[0]), "r"(a[1]), "r"(a[2]), "r"(a[3]), "r"(b[0]), "r"(b[1]));
}
__device__ __forceinline__ void ldsm4(uint32_t* r, uint32_t saddr) {
    asm volatile("ldmatrix.sync.aligned.m8n8.x4.shared.b16 {%0,%1,%2,%3}, [%4];"
                 : "=r"(r[0]), "=r"(r[1]), "=r"(r[2]), "=r"(r[3]) : "r"(saddr));
}
__device__ __forceinline__ void cpa16(uint32_t dst, const void* src) {
    asm volatile("cp.async.ca.shared.global [%0], [%1], 16;" :: "r"(dst), "l"(src));
}
#define CP_COMMIT asm volatile("cp.async.commit_group;")
#define CP_WAIT0  asm volatile("cp.async.wait_group 0;")

// ---------------------------------------------------------------------------
// pre-round: out[i] = tf32(in[i])
// ---------------------------------------------------------------------------
__global__ void round_kernel(const float4* __restrict__ in, float4* __restrict__ out,
                             int n4)
{
    int i = blockIdx.x * blockDim.x + threadIdx.x;
    if (i < n4) {
        float4 v = in[i];
        v.x = tf32r(v.x); v.y = tf32r(v.y); v.z = tf32r(v.z); v.w = tf32r(v.w);
        out[i] = v;
    }
}

// ---------------------------------------------------------------------------
// TF32 GEMM NT, 2-stage cp.async pipeline (R13 configuration).
// MODE 0: plain store. MODE 1: tf32-rounded scatter to g_qkv.
// ---------------------------------------------------------------------------
#define ASZ (128 * 36)          // floats per stage per operand

template <int MODE>
__global__ __launch_bounds__(256)
void gemm_tf32(const float* __restrict__ A, const float* __restrict__ Bw,
               const float* __restrict__ bias, float* __restrict__ Cout,
               int M, int N, int K)
{
    extern __shared__ float sm[];
    float* As = sm;             // 2 stages
    float* Bs = sm + 2 * ASZ;   // 2 stages

    const int bm = blockIdx.y * 128;
    const int bn = blockIdx.x * 128;
    const int tid = threadIdx.x;
    const int lane = tid & 31;
    const int warp = tid >> 5;
    const int wm = (warp >> 2) * 64;
    const int wn = (warp & 3) * 32;

    float acc[4][4][4] = {};

    const int lrow = tid >> 3;          // 0..31
    const int lcol = (tid & 7) * 4;     // 0..28

    const uint32_t uA = (uint32_t)__cvta_generic_to_shared(As);
    const uint32_t uB = (uint32_t)__cvta_generic_to_shared(Bs);
    const uint32_t aA = uA + (((wm + (lane & 15)) * 36 + (lane >> 4) * 4) << 2);
    const uint32_t aB = uB + (((wn + (lane & 7) + ((lane >> 4) << 3)) * 36
                               + ((lane >> 3) & 1) * 4) << 2);
    const uint32_t dA = uA + ((lrow * 36 + lcol) << 2);
    const uint32_t dB = uB + ((lrow * 36 + lcol) << 2);

    const int nk = K / 32;

    // prologue: stage 0
#pragma unroll
    for (int p = 0; p < 4; p++) {
        cpa16(dA + p * (32 * 36 * 4), &A[(size_t)(bm + lrow + p * 32) * K + lcol]);
        cpa16(dB + p * (32 * 36 * 4), &Bw[(size_t)(bn + lrow + p * 32) * K + lcol]);
    }
    CP_COMMIT;

    for (int i = 0; i < nk; i++) {
        CP_WAIT0;
        __syncthreads();
        const int s = i & 1;
        if (i + 1 < nk) {
            const int k1 = (i + 1) * 32;
            const uint32_t so = (uint32_t)((s ^ 1) * ASZ * 4);
#pragma unroll
            for (int p = 0; p < 4; p++) {
                cpa16(dA + so + p * (32 * 36 * 4),
                      &A[(size_t)(bm + lrow + p * 32) * K + k1 + lcol]);
                cpa16(dB + so + p * (32 * 36 * 4),
                      &Bw[(size_t)(bn + lrow + p * 32) * K + k1 + lcol]);
            }
            CP_COMMIT;
        }
        const uint32_t co = (uint32_t)(s * ASZ * 4);
#pragma unroll
        for (int ks = 0; ks < 4; ks++) {
            uint32_t af[4][4];
#pragma unroll
            for (int mi = 0; mi < 4; mi++)
                ldsm4(af[mi], aA + co + mi * (16 * 36 * 4) + ks * 32);
#pragma unroll
            for (int njp = 0; njp < 2; njp++) {
                uint32_t b4[4];
                ldsm4(b4, aB + co + njp * (16 * 36 * 4) + ks * 32);
#pragma unroll
                for (int mi = 0; mi < 4; mi++) {
                    mma_tf32(acc[mi][2 * njp + 0], af[mi], b4);
                    mma_tf32(acc[mi][2 * njp + 1], af[mi], b4 + 2);
                }
            }
        }
        __syncthreads();
    }

    // epilogue
#pragma unroll
    for (int mi = 0; mi < 4; mi++) {
        const int r0 = bm + wm + mi * 16 + (lane >> 2);
#pragma unroll
        for (int nj = 0; nj < 4; nj++) {
            const int c = bn + wn + nj * 8 + 2 * (lane & 3);
            const float b0 = bias[c], b1 = bias[c + 1];
            float v00 = acc[mi][nj][0] + b0, v01 = acc[mi][nj][1] + b1;
            float v10 = acc[mi][nj][2] + b0, v11 = acc[mi][nj][3] + b1;
            if (MODE == 0) {
                *(float2*)&Cout[(size_t)r0 * N + c] = make_float2(v00, v01);
                *(float2*)&Cout[(size_t)(r0 + 8) * N + c] = make_float2(v10, v11);
            } else {
                v00 = tf32r(v00); v01 = tf32r(v01);
                v10 = tf32r(v10); v11 = tf32r(v11);
#pragma unroll
                for (int e = 0; e < 2; e++) {
                    const int n = c + e;
                    const int which = n / CC;
                    const int rem = n - which * CC;
                    const int hh = rem >> 6;
                    const int dd = rem & 63;
#pragma unroll
                    for (int rr = 0; rr < 2; rr++) {
                        const int m = r0 + rr * 8;
                        const int bb = m / TT;
                        const int t = m - bb * TT;
                        const size_t off =
                            ((((size_t)which * BB + bb) * HH + hh) * TT + t) * DD + dd;
                        g_qkv[off] = (rr == 0) ? (e == 0 ? v00 : v01)
                                               : (e == 0 ? v10 : v11);
                    }
                }
            }
        }
    }
}

// ---------------------------------------------------------------------------
// TF32 mma flash attention, q-tile 128 (8 warps / 256 threads), Bc = 64,
// 2-stage cp.async K/V pipeline. Per-warp skip/diag handling for the wider
// diagonal band (fully-masked tiles MUST be skipped: otherwise mn stays
// -1e30 and p = ex2(0) = 1 corrupts the accumulator).
// smem floats: Qs[128*68] | Ks[2][64*68] | Vs[2][64*72] | mask[2][64]
// ---------------------------------------------------------------------------
#define QST 68
#define KST 68
#define VST 72
#define QS_OFF 0
#define KS_OFF (128 * QST)                  // 8704
#define VS_OFF (KS_OFF + 2 * 64 * KST)      // 17408
#define MK_OFF (VS_OFF + 2 * 64 * VST)      // 26624
#define SC_LOG2 0.18033688011112042f        // 0.125 * log2(e)
#define ATTN_SMEM ((MK_OFF + 2 * 64) * 4)   // 107008 B

__global__ __launch_bounds__(256)
void attn_tf32(const int* __restrict__ amask, float* __restrict__ ctx)
{
    extern __shared__ float smf[];
    float* Qs = smf + QS_OFF;
    int* mks = (int*)(smf + MK_OFF);

    const int qb = blockIdx.x;              // 0..15, q-tile of 128 rows
    const int bh = blockIdx.y;
    const int b = bh / HH, h = bh % HH;
    const bool causal = (h < NLEFT);
    const int tid = threadIdx.x, lane = tid & 31, warp = tid >> 5;

    const float* Qp = g_qkv + ((size_t)b * HH + h) * (size_t)TT * DD;
    const float* Kp = g_qkv + (size_t)BB * HH * TT * DD
                    + ((size_t)b * HH + h) * (size_t)TT * DD;
    const float* Vp = g_qkv + 2ull * BB * HH * TT * DD
                    + ((size_t)b * HH + h) * (size_t)TT * DD;
    const int q0 = qb * 128;

    const uint32_t uS = (uint32_t)__cvta_generic_to_shared(smf);
    const uint32_t aQ = uS + (((warp * 16 + (lane & 15)) * QST + (lane >> 4) * 4) << 2);
    const uint32_t aK = uS + (KS_OFF << 2)
        + ((((lane & 7) + ((lane >> 4) << 3)) * KST + ((lane >> 3) & 1) * 4) << 2);
    // cp.async destinations (256 threads: 16 rows x 16 float4 per pass)
    const int clin_row = tid >> 4;             // 0..15
    const int clin_f4 = (tid & 15) * 4;
    const uint32_t dK = uS + (KS_OFF << 2) + ((clin_row * KST + clin_f4) << 2);
    const uint32_t dV = uS + (VS_OFF << 2) + ((clin_row * VST + clin_f4) << 2);
    const uint32_t dM = uS + (MK_OFF << 2) + (tid << 4);

    const int ktb = causal ? 0 : 2 * qb;
    const int kte = causal ? (2 * qb + 2) : (TT / 64);

    auto issue = [&](int kt, int s) {
        const uint32_t so = (uint32_t)(s * 64 * KST * 4);
        const uint32_t sov = (uint32_t)(s * 64 * VST * 4);
#pragma unroll
        for (int u = 0; u < 4; u++) {
            const int row = clin_row + u * 16;
            cpa16(dK + so + u * (16 * KST * 4),
                  &Kp[(size_t)(kt * 64 + row) * DD + clin_f4]);
            cpa16(dV + sov + u * (16 * VST * 4),
                  &Vp[(size_t)(kt * 64 + row) * DD + clin_f4]);
        }
        if (tid < 16) cpa16(dM + s * 256, &amask[b * TT + kt * 64 + tid * 4]);
        CP_COMMIT;
    };

    issue(ktb, 0);

    // stage Q tile (scale by 0.125*log2e, round) — overlaps stage-0 cp.async
#pragma unroll
    for (int u = 0; u < 8; u++) {
        const int linear = u * 256 + tid;
        const int row = linear >> 4, f4 = (linear & 15) * 4;
        float4 v = *(const float4*)&Qp[(size_t)(q0 + row) * DD + f4];
        float* d = &Qs[row * QST + f4];
        d[0] = tf32r(v.x * SC_LOG2); d[1] = tf32r(v.y * SC_LOG2);
        d[2] = tf32r(v.z * SC_LOG2); d[3] = tf32r(v.w * SC_LOG2);
    }
    __syncthreads();

    uint32_t qa[8][4];
#pragma unroll
    for (int kf = 0; kf < 8; kf++) ldsm4(qa[kf], aQ + kf * 32);

    float oc[8][4] = {};
    float m0 = -1e30f, m1 = -1e30f, l0 = 0.f, l1 = 0.f;
    const int row_min = q0 + warp * 16;
    const int qrA = row_min + (lane >> 2);
    const int qrB = qrA + 8;
    const int rps = warp * 16 + (lane >> 2);

    for (int kt = ktb; kt < kte; kt++) {
        const int s = (kt - ktb) & 1;
        CP_WAIT0;
        __syncthreads();
        if (kt + 1 < kte) issue(kt + 1, s ^ 1);

        // per-warp: tile fully on the wrong side of this warp's diagonal?
        const bool skip = causal ? (kt * 64 > row_min + 15)
                                 : (kt * 64 + 63 < row_min);
        if (!skip) {
            const int* mk = mks + s * 64;
            const int mv0l = mk[lane], mv1l = mk[lane + 32];
            const bool allv = __all_sync(0xffffffffu, (mv0l != 0) && (mv1l != 0));
            const uint32_t co = (uint32_t)(s * 64 * KST * 4);
            const float* Vst = smf + VS_OFF + s * 64 * VST;

            // S = Q K^T (log2 units)
            float sc[8][4] = {};
#pragma unroll
            for (int njp = 0; njp < 4; njp++) {
#pragma unroll
                for (int kf = 0; kf < 8; kf++) {
                    uint32_t b4[4];
                    ldsm4(b4, aK + co + njp * (16 * KST * 4) + kf * 32);
                    mma_tf32(sc[2 * njp + 0], qa[kf], b4);
                    mma_tf32(sc[2 * njp + 1], qa[kf], b4 + 2);
                }
            }

            // per-warp diagonal band?
            const bool diag = causal ? (kt * 64 + 63 > row_min)
                                     : (kt * 64 < row_min + 15);
            float tmax0 = -1e30f, tmax1 = -1e30f;
            if (allv && !diag) {
#pragma unroll
                for (int nj = 0; nj < 8; nj++) {
                    tmax0 = fmaxf(tmax0, fmaxf(sc[nj][0], sc[nj][1]));
                    tmax1 = fmaxf(tmax1, fmaxf(sc[nj][2], sc[nj][3]));
                }
            } else {
#pragma unroll
                for (int nj = 0; nj < 8; nj++) {
                    const int kl = nj * 8 + 2 * (lane & 3);
                    const int key = kt * 64 + kl;
                    const int mv0 = mk[kl], mv1 = mk[kl + 1];
                    float s0 = sc[nj][0], s1 = sc[nj][1];
                    float s2 = sc[nj][2], s3 = sc[nj][3];
                    bool bd0A = (mv0 == 0), bd1A = (mv1 == 0);
                    bool bd0B = bd0A, bd1B = bd1A;
                    if (diag) {
                        if (causal) {
                            bd0A |= (key > qrA); bd1A |= (key + 1 > qrA);
                            bd0B |= (key > qrB); bd1B |= (key + 1 > qrB);
                        } else {
                            bd0A |= (key < qrA); bd1A |= (key + 1 < qrA);
                            bd0B |= (key < qrB); bd1B |= (key + 1 < qrB);
                        }
                    }
                    s0 = bd0A ? -1e30f : s0; s1 = bd1A ? -1e30f : s1;
                    s2 = bd0B ? -1e30f : s2; s3 = bd1B ? -1e30f : s3;
                    sc[nj][0] = s0; sc[nj][1] = s1; sc[nj][2] = s2; sc[nj][3] = s3;
                    tmax0 = fmaxf(tmax0, fmaxf(s0, s1));
                    tmax1 = fmaxf(tmax1, fmaxf(s2, s3));
                }
            }
            tmax0 = fmaxf(tmax0, __shfl_xor_sync(0xffffffffu, tmax0, 1));
            tmax0 = fmaxf(tmax0, __shfl_xor_sync(0xffffffffu, tmax0, 2));
            tmax1 = fmaxf(tmax1, __shfl_xor_sync(0xffffffffu, tmax1, 1));
            tmax1 = fmaxf(tmax1, __shfl_xor_sync(0xffffffffu, tmax1, 2));

            const float mn0 = fmaxf(m0, tmax0), mn1 = fmaxf(m1, tmax1);
            const float cr0 = ex2(m0 - mn0), cr1 = ex2(m1 - mn1);
            m0 = mn0; m1 = mn1;
            l0 *= cr0; l1 *= cr1;
#pragma unroll
            for (int nj = 0; nj < 8; nj++) {
                oc[nj][0] *= cr0; oc[nj][1] *= cr0;
                oc[nj][2] *= cr1; oc[nj][3] *= cr1;
            }

            // P = 2^(S - m) -> Qs (warp-private rows)
#pragma unroll
            for (int nj = 0; nj < 8; nj++) {
                const int kl = nj * 8 + 2 * (lane & 3);
                float p0 = ex2(sc[nj][0] - mn0), p1 = ex2(sc[nj][1] - mn0);
                float p2 = ex2(sc[nj][2] - mn1), p3 = ex2(sc[nj][3] - mn1);
                l0 += p0 + p1; l1 += p2 + p3;
                *(float2*)&Qs[rps * QST + kl] = make_float2(tf32r(p0), tf32r(p1));
                *(float2*)&Qs[(rps + 8) * QST + kl] = make_float2(tf32r(p2), tf32r(p3));
            }
            __syncwarp();

            // O += P V
#pragma unroll
            for (int kf = 0; kf < 8; kf++) {
                uint32_t pa[4];
                ldsm4(pa, aQ + kf * 32);
                const int c0 = kf * 8 + (lane & 3);
#pragma unroll
                for (int nj = 0; nj < 8; nj++) {
                    const int n0 = nj * 8 + (lane >> 2);
                    uint32_t vb[2];
                    vb[0] = __float_as_uint(Vst[c0 * VST + n0]);
                    vb[1] = __float_as_uint(Vst[(c0 + 4) * VST + n0]);
                    mma_tf32(oc[nj], pa, vb);
                }
            }
        }
        __syncthreads();   // all warps done with stage s before it is refilled
    }

    l0 += __shfl_xor_sync(0xffffffffu, l0, 1);
    l0 += __shfl_xor_sync(0xffffffffu, l0, 2);
    l1 += __shfl_xor_sync(0xffffffffu, l1, 1);
    l1 += __shfl_xor_sync(0xffffffffu, l1, 2);
    const float i0 = 1.f / l0, i1 = 1.f / l1;

#pragma unroll
    for (int nj = 0; nj < 8; nj++) {
        const int d = nj * 8 + 2 * (lane & 3);
        *(float2*)&ctx[((size_t)b * TT + qrA) * CC + h * DD + d] =
            make_float2(tf32r(oc[nj][0] * i0), tf32r(oc[nj][1] * i0));
        *(float2*)&ctx[((size_t)b * TT + qrB) * CC + h * DD + d] =
            make_float2(tf32r(oc[nj][2] * i1), tf32r(oc[nj][3] * i1));
    }
}

// ---------------------------------------------------------------------------
extern "C" void kernel_launch(void* const* d_in, const int* in_sizes, int n_in,
                              void* d_out, int out_size)
{
    const float* x      = (const float*)d_in[0];
    const int*   amask  = (const int*)d_in[1];
    const float* Wqkv_w = (const float*)d_in[2];
    const float* Wqkv_b = (const float*)d_in[3];
    const float* Wo_w   = (const float*)d_in[4];
    const float* Wo_b   = (const float*)d_in[5];
    float* out = (float*)d_out;

    float *d_ctx, *d_xr, *d_wqkv, *d_wo;
    cudaGetSymbolAddress((void**)&d_ctx, g_ctx);
    cudaGetSymbolAddress((void**)&d_xr, g_xr);
    cudaGetSymbolAddress((void**)&d_wqkv, g_wqkv);
    cudaGetSymbolAddress((void**)&d_wo, g_wo);

    const int GEMM_SMEM = 4 * ASZ * 4;   // 73728 B (2 stages x 2 operands)
    cudaFuncSetAttribute(gemm_tf32<0>, cudaFuncAttributeMaxDynamicSharedMemorySize,
                         GEMM_SMEM);
    cudaFuncSetAttribute(gemm_tf32<1>, cudaFuncAttributeMaxDynamicSharedMemorySize,
                         GEMM_SMEM);
    cudaFuncSetAttribute(attn_tf32, cudaFuncAttributeMaxDynamicSharedMemorySize,
                         ATTN_SMEM);

    // 0) pre-round x / Wqkv / Wo to tf32
    {
        const int n1 = MM * CC / 4, n2 = NQKV * CC / 4, n3 = CC * CC / 4;
        round_kernel<<<(n1 + 255) / 256, 256>>>((const float4*)x, (float4*)d_xr, n1);
        round_kernel<<<(n2 + 255) / 256, 256>>>((const float4*)Wqkv_w, (float4*)d_wqkv, n2);
        round_kernel<<<(n3 + 255) / 256, 256>>>((const float4*)Wo_w, (float4*)d_wo, n3);
    }
    // 1) QKV projection -> g_qkv (tf32-rounded)
    {
        dim3 grid(NQKV / 128, MM / 128);   // (18, 32)
        gemm_tf32<1><<<grid, 256, GEMM_SMEM>>>(d_xr, d_wqkv, Wqkv_b, nullptr,
                                               MM, NQKV, CC);
    }
    // 2) attention -> g_ctx (tf32-rounded)
    {
        dim3 grid(TT / 128, BB * HH);      // (16, 24)
        attn_tf32<<<grid, 256, ATTN_SMEM>>>(amask, d_ctx);
    }
    // 3) output projection -> out (fp32)
    {
        dim3 grid(CC / 128, MM / 128);     // (6, 32)
        gemm_tf32<0><<<grid, 256, GEMM_SMEM>>>(d_ctx, d_wo, Wo_b, out, MM, CC, CC);
    }
}

// round 17
// speedup vs baseline: 1.1113x; 1.0428x over previous
#include <cuda_runtime.h>
#include <cuda_bf16.h>
#include <math.h>
#include <stdint.h>

#define BB 2
#define TT 2048
#define CC 768
#define HH 12
#define DD 64
#define NLEFT 6
#define NQKV (3 * CC)   // 2304
#define MM (BB * TT)    // 4096

// Scratch: qkv in [which][b][h][t][d], ctx in [B][T][C]
__device__ float g_qkv[3ull * BB * HH * TT * DD];
__device__ float g_ctx[(size_t)BB * TT * CC];
__device__ float g_xr[(size_t)MM * CC];
__device__ float g_wqkv[(size_t)NQKV * CC];
__device__ float g_wo[(size_t)CC * CC];

// ---------------------------------------------------------------------------
// helpers
// ---------------------------------------------------------------------------
__device__ __forceinline__ float tf32r(float f) {
    uint32_t u;
    asm("cvt.rna.tf32.f32 %0, %1;" : "=r"(u) : "f"(f));
    return __uint_as_float(u);
}
__device__ __forceinline__ float ex2(float x) {
    float y;
    asm("ex2.approx.ftz.f32 %0, %1;" : "=f"(y) : "f"(x));
    return y;
}
__device__ __forceinline__ void mma_tf32(float* c, const uint32_t* a, const uint32_t* b) {
    asm("mma.sync.aligned.m16n8k8.row.col.f32.tf32.tf32.f32 "
        "{%0,%1,%2,%3}, {%4,%5,%6,%7}, {%8,%9}, {%0,%1,%2,%3};"
        : "+f"(c[0]), "+f"(c[1]), "+f"(c[2]), "+f"(c[3])
        : "r"(a[0]), "r"(a[1]), "r"(a[2]), "r"(a[3]), "r"(b[0]), "r"(b[1]));
}
__device__ __forceinline__ void ldsm4(uint32_t* r, uint32_t saddr) {
    asm volatile("ldmatrix.sync.aligned.m8n8.x4.shared.b16 {%0,%1,%2,%3}, [%4];"
                 : "=r"(r[0]), "=r"(r[1]), "=r"(r[2]), "=r"(r[3]) : "r"(saddr));
}
__device__ __forceinline__ void cpa16(uint32_t dst, const void* src) {
    asm volatile("cp.async.ca.shared.global [%0], [%1], 16;" :: "r"(dst), "l"(src));
}
#define CP_COMMIT asm volatile("cp.async.commit_group;")
#define CP_WAIT0  asm volatile("cp.async.wait_group 0;")

// ---------------------------------------------------------------------------
// pre-round: out[i] = tf32(in[i])
// ---------------------------------------------------------------------------
__global__ void round_kernel(const float4* __restrict__ in, float4* __restrict__ out,
                             int n4)
{
    int i = blockIdx.x * blockDim.x + threadIdx.x;
    if (i < n4) {
        float4 v = in[i];
        v.x = tf32r(v.x); v.y = tf32r(v.y); v.z = tf32r(v.z); v.w = tf32r(v.w);
        out[i] = v;
    }
}

// ---------------------------------------------------------------------------
// TF32 GEMM NT, 2-stage cp.async pipeline (R13 configuration — keeper).
// MODE 0: plain store. MODE 1: tf32-rounded scatter to g_qkv.
// ---------------------------------------------------------------------------
#define ASZ (128 * 36)          // floats per stage per operand

template <int MODE>
__global__ __launch_bounds__(256)
void gemm_tf32(const float* __restrict__ A, const float* __restrict__ Bw,
               const float* __restrict__ bias, float* __restrict__ Cout,
               int M, int N, int K)
{
    extern __shared__ float sm[];
    float* As = sm;             // 2 stages
    float* Bs = sm + 2 * ASZ;   // 2 stages

    const int bm = blockIdx.y * 128;
    const int bn = blockIdx.x * 128;
    const int tid = threadIdx.x;
    const int lane = tid & 31;
    const int warp = tid >> 5;
    const int wm = (warp >> 2) * 64;
    const int wn = (warp & 3) * 32;

    float acc[4][4][4] = {};

    const int lrow = tid >> 3;          // 0..31
    const int lcol = (tid & 7) * 4;     // 0..28

    const uint32_t uA = (uint32_t)__cvta_generic_to_shared(As);
    const uint32_t uB = (uint32_t)__cvta_generic_to_shared(Bs);
    const uint32_t aA = uA + (((wm + (lane & 15)) * 36 + (lane >> 4) * 4) << 2);
    const uint32_t aB = uB + (((wn + (lane & 7) + ((lane >> 4) << 3)) * 36
                               + ((lane >> 3) & 1) * 4) << 2);
    const uint32_t dA = uA + ((lrow * 36 + lcol) << 2);
    const uint32_t dB = uB + ((lrow * 36 + lcol) << 2);

    const int nk = K / 32;

    // prologue: stage 0
#pragma unroll
    for (int p = 0; p < 4; p++) {
        cpa16(dA + p * (32 * 36 * 4), &A[(size_t)(bm + lrow + p * 32) * K + lcol]);
        cpa16(dB + p * (32 * 36 * 4), &Bw[(size_t)(bn + lrow + p * 32) * K + lcol]);
    }
    CP_COMMIT;

    for (int i = 0; i < nk; i++) {
        CP_WAIT0;
        __syncthreads();
        const int s = i & 1;
        if (i + 1 < nk) {
            const int k1 = (i + 1) * 32;
            const uint32_t so = (uint32_t)((s ^ 1) * ASZ * 4);
#pragma unroll
            for (int p = 0; p < 4; p++) {
                cpa16(dA + so + p * (32 * 36 * 4),
                      &A[(size_t)(bm + lrow + p * 32) * K + k1 + lcol]);
                cpa16(dB + so + p * (32 * 36 * 4),
                      &Bw[(size_t)(bn + lrow + p * 32) * K + k1 + lcol]);
            }
            CP_COMMIT;
        }
        const uint32_t co = (uint32_t)(s * ASZ * 4);
#pragma unroll
        for (int ks = 0; ks < 4; ks++) {
            uint32_t af[4][4];
#pragma unroll
            for (int mi = 0; mi < 4; mi++)
                ldsm4(af[mi], aA + co + mi * (16 * 36 * 4) + ks * 32);
#pragma unroll
            for (int njp = 0; njp < 2; njp++) {
                uint32_t b4[4];
                ldsm4(b4, aB + co + njp * (16 * 36 * 4) + ks * 32);
#pragma unroll
                for (int mi = 0; mi < 4; mi++) {
                    mma_tf32(acc[mi][2 * njp + 0], af[mi], b4);
                    mma_tf32(acc[mi][2 * njp + 1], af[mi], b4 + 2);
                }
            }
        }
        __syncthreads();
    }

    // epilogue
#pragma unroll
    for (int mi = 0; mi < 4; mi++) {
        const int r0 = bm + wm + mi * 16 + (lane >> 2);
#pragma unroll
        for (int nj = 0; nj < 4; nj++) {
            const int c = bn + wn + nj * 8 + 2 * (lane & 3);
            const float b0 = bias[c], b1 = bias[c + 1];
            float v00 = acc[mi][nj][0] + b0, v01 = acc[mi][nj][1] + b1;
            float v10 = acc[mi][nj][2] + b0, v11 = acc[mi][nj][3] + b1;
            if (MODE == 0) {
                *(float2*)&Cout[(size_t)r0 * N + c] = make_float2(v00, v01);
                *(float2*)&Cout[(size_t)(r0 + 8) * N + c] = make_float2(v10, v11);
            } else {
                v00 = tf32r(v00); v01 = tf32r(v01);
                v10 = tf32r(v10); v11 = tf32r(v11);
#pragma unroll
                for (int e = 0; e < 2; e++) {
                    const int n = c + e;
                    const int which = n / CC;
                    const int rem = n - which * CC;
                    const int hh = rem >> 6;
                    const int dd = rem & 63;
#pragma unroll
                    for (int rr = 0; rr < 2; rr++) {
                        const int m = r0 + rr * 8;
                        const int bb = m / TT;
                        const int t = m - bb * TT;
                        const size_t off =
                            ((((size_t)which * BB + bb) * HH + hh) * TT + t) * DD + dd;
                        g_qkv[off] = (rr == 0) ? (e == 0 ? v00 : v01)
                                               : (e == 0 ? v10 : v11);
                    }
                }
            }
        }
    }
}

// ---------------------------------------------------------------------------
// TF32 mma flash attention: 4 warps x 32 q-rows/warp (Br=128), Bc=64,
// 2-stage cp.async K/V. Each warp's two m16 row-groups share every K
// fragment and every V load -> ~1.8x less smem traffic per q-row.
// Q fragments register-resident; Qs buffer reused for P.
// smem floats: Qs[128*68] | Ks[2][64*68] | Vs[2][64*72] | mask[2][64]
// ---------------------------------------------------------------------------
#define QST 68
#define KST 68
#define VST 72
#define QS_OFF 0
#define KS_OFF (128 * QST)                  // 8704
#define VS_OFF (KS_OFF + 2 * 64 * KST)      // 17408
#define MK_OFF (VS_OFF + 2 * 64 * VST)      // 26624
#define SC_LOG2 0.18033688011112042f        // 0.125 * log2(e)
#define ATTN_SMEM ((MK_OFF + 2 * 64) * 4)   // 107008 B

__global__ __launch_bounds__(128)
void attn_tf32(const int* __restrict__ amask, float* __restrict__ ctx)
{
    extern __shared__ float smf[];
    float* Qs = smf + QS_OFF;          // 128 x QST, reused as P
    int* mks = (int*)(smf + MK_OFF);

    const int qb = blockIdx.x;          // 0..15, q-tile of 128 rows
    const int bh = blockIdx.y;
    const int b = bh / HH, h = bh % HH;
    const bool causal = (h < NLEFT);
    const int tid = threadIdx.x, lane = tid & 31, warp = tid >> 5;

    const float* Qp = g_qkv + ((size_t)b * HH + h) * (size_t)TT * DD;
    const float* Kp = g_qkv + (size_t)BB * HH * TT * DD
                    + ((size_t)b * HH + h) * (size_t)TT * DD;
    const float* Vp = g_qkv + 2ull * BB * HH * TT * DD
                    + ((size_t)b * HH + h) * (size_t)TT * DD;
    const int q0 = qb * 128;

    const uint32_t uS = (uint32_t)__cvta_generic_to_shared(smf);
    const uint32_t aQ0 = uS + (((warp * 32 + (lane & 15)) * QST + (lane >> 4) * 4) << 2);
    const uint32_t aQ1 = aQ0 + 16 * QST * 4;
    const uint32_t aK = uS + (KS_OFF << 2)
        + ((((lane & 7) + ((lane >> 4) << 3)) * KST + ((lane >> 3) & 1) * 4) << 2);
    // cp.async destinations (128 threads: 8 rows x 16 float4 per pass)
    const int clin_row = tid >> 4;             // 0..7
    const int clin_f4 = (tid & 15) * 4;
    const uint32_t dK = uS + (KS_OFF << 2) + ((clin_row * KST + clin_f4) << 2);
    const uint32_t dV = uS + (VS_OFF << 2) + ((clin_row * VST + clin_f4) << 2);
    const uint32_t dM = uS + (MK_OFF << 2) + (tid << 4);

    const int ktb = causal ? 0 : 2 * qb;
    const int kte = causal ? (2 * qb + 2) : (TT / 64);

    auto issue = [&](int kt, int s) {
        const uint32_t so = (uint32_t)(s * 64 * KST * 4);
        const uint32_t sov = (uint32_t)(s * 64 * VST * 4);
#pragma unroll
        for (int u = 0; u < 8; u++) {
            const int row = clin_row + u * 8;
            cpa16(dK + so + u * (8 * KST * 4),
                  &Kp[(size_t)(kt * 64 + row) * DD + clin_f4]);
            cpa16(dV + sov + u * (8 * VST * 4),
                  &Vp[(size_t)(kt * 64 + row) * DD + clin_f4]);
        }
        if (tid < 16) cpa16(dM + s * 256, &amask[b * TT + kt * 64 + tid * 4]);
        CP_COMMIT;
    };

    issue(ktb, 0);

    // stage Q tile (128 rows; scale by 0.125*log2e, round) — overlaps cp.async
#pragma unroll
    for (int u = 0; u < 16; u++) {
        const int linear = u * 128 + tid;
        const int row = linear >> 4, f4 = (linear & 15) * 4;
        float4 v = *(const float4*)&Qp[(size_t)(q0 + row) * DD + f4];
        float* d = &Qs[row * QST + f4];
        d[0] = tf32r(v.x * SC_LOG2); d[1] = tf32r(v.y * SC_LOG2);
        d[2] = tf32r(v.z * SC_LOG2); d[3] = tf32r(v.w * SC_LOG2);
    }
    __syncthreads();

    // register-resident Q fragments (2 row-groups x 8 k-steps)
    uint32_t qa[2][8][4];
#pragma unroll
    for (int kf = 0; kf < 8; kf++) {
        ldsm4(qa[0][kf], aQ0 + kf * 32);
        ldsm4(qa[1][kf], aQ1 + kf * 32);
    }

    float oc[2][8][4] = {};
    float mrow[2][2], lsum[2][2];
#pragma unroll
    for (int mi = 0; mi < 2; mi++) {
        mrow[mi][0] = -1e30f; mrow[mi][1] = -1e30f;
        lsum[mi][0] = 0.f;    lsum[mi][1] = 0.f;
    }
    const int row_min = q0 + warp * 32;
    const int rps0 = warp * 32 + (lane >> 2);

    for (int kt = ktb; kt < kte; kt++) {
        const int s = (kt - ktb) & 1;
        CP_WAIT0;
        __syncthreads();       // stage s ready; all warps done with stage s^1
        if (kt + 1 < kte) issue(kt + 1, s ^ 1);

        // per-warp: tile fully on the wrong side of this warp's 32-row band?
        const bool skip = causal ? (kt * 64 > row_min + 31)
                                 : (kt * 64 + 63 < row_min);
        if (!skip) {
            const int* mk = mks + s * 64;
            const int mv0l = mk[lane], mv1l = mk[lane + 32];
            const bool allv = __all_sync(0xffffffffu, (mv0l != 0) && (mv1l != 0));
            const uint32_t co = (uint32_t)(s * 64 * KST * 4);
            const float* Vst = smf + VS_OFF + s * 64 * VST;

            // S = Q K^T for both row-groups; K fragments shared
            float sc[2][8][4] = {};
#pragma unroll
            for (int kf = 0; kf < 8; kf++) {
#pragma unroll
                for (int njp = 0; njp < 4; njp++) {
                    uint32_t b4[4];
                    ldsm4(b4, aK + co + njp * (16 * KST * 4) + kf * 32);
                    mma_tf32(sc[0][2 * njp + 0], qa[0][kf], b4);
                    mma_tf32(sc[0][2 * njp + 1], qa[0][kf], b4 + 2);
                    mma_tf32(sc[1][2 * njp + 0], qa[1][kf], b4);
                    mma_tf32(sc[1][2 * njp + 1], qa[1][kf], b4 + 2);
                }
            }

            const bool diag = causal ? (kt * 64 + 63 > row_min)
                                     : (kt * 64 < row_min + 31);
#pragma unroll
            for (int mi = 0; mi < 2; mi++) {
                const int qrA = row_min + mi * 16 + (lane >> 2);
                const int qrB = qrA + 8;
                float tmax0 = -1e30f, tmax1 = -1e30f;
                if (allv && !diag) {
#pragma unroll
                    for (int nj = 0; nj < 8; nj++) {
                        tmax0 = fmaxf(tmax0, fmaxf(sc[mi][nj][0], sc[mi][nj][1]));
                        tmax1 = fmaxf(tmax1, fmaxf(sc[mi][nj][2], sc[mi][nj][3]));
                    }
                } else {
#pragma unroll
                    for (int nj = 0; nj < 8; nj++) {
                        const int kl = nj * 8 + 2 * (lane & 3);
                        const int key = kt * 64 + kl;
                        const int mv0 = mk[kl], mv1 = mk[kl + 1];
                        float s0 = sc[mi][nj][0], s1 = sc[mi][nj][1];
                        float s2 = sc[mi][nj][2], s3 = sc[mi][nj][3];
                        bool bd0A = (mv0 == 0), bd1A = (mv1 == 0);
                        bool bd0B = bd0A, bd1B = bd1A;
                        if (diag) {
                            if (causal) {
                                bd0A |= (key > qrA); bd1A |= (key + 1 > qrA);
                                bd0B |= (key > qrB); bd1B |= (key + 1 > qrB);
                            } else {
                                bd0A |= (key < qrA); bd1A |= (key + 1 < qrA);
                                bd0B |= (key < qrB); bd1B |= (key + 1 < qrB);
                            }
                        }
                        s0 = bd0A ? -1e30f : s0; s1 = bd1A ? -1e30f : s1;
                        s2 = bd0B ? -1e30f : s2; s3 = bd1B ? -1e30f : s3;
                        sc[mi][nj][0] = s0; sc[mi][nj][1] = s1;
                        sc[mi][nj][2] = s2; sc[mi][nj][3] = s3;
                        tmax0 = fmaxf(tmax0, fmaxf(s0, s1));
                        tmax1 = fmaxf(tmax1, fmaxf(s2, s3));
                    }
                }
                tmax0 = fmaxf(tmax0, __shfl_xor_sync(0xffffffffu, tmax0, 1));
                tmax0 = fmaxf(tmax0, __shfl_xor_sync(0xffffffffu, tmax0, 2));
                tmax1 = fmaxf(tmax1, __shfl_xor_sync(0xffffffffu, tmax1, 1));
                tmax1 = fmaxf(tmax1, __shfl_xor_sync(0xffffffffu, tmax1, 2));

                const float mn0 = fmaxf(mrow[mi][0], tmax0);
                const float mn1 = fmaxf(mrow[mi][1], tmax1);
                const float cr0 = ex2(mrow[mi][0] - mn0);
                const float cr1 = ex2(mrow[mi][1] - mn1);
                mrow[mi][0] = mn0; mrow[mi][1] = mn1;
                lsum[mi][0] *= cr0; lsum[mi][1] *= cr1;
#pragma unroll
                for (int nj = 0; nj < 8; nj++) {
                    oc[mi][nj][0] *= cr0; oc[mi][nj][1] *= cr0;
                    oc[mi][nj][2] *= cr1; oc[mi][nj][3] *= cr1;
                }

                // P = 2^(S - m) -> Qs (warp-private rows)
                const int rps = rps0 + mi * 16;
#pragma unroll
                for (int nj = 0; nj < 8; nj++) {
                    const int kl = nj * 8 + 2 * (lane & 3);
                    float p0 = ex2(sc[mi][nj][0] - mn0);
                    float p1 = ex2(sc[mi][nj][1] - mn0);
                    float p2 = ex2(sc[mi][nj][2] - mn1);
                    float p3 = ex2(sc[mi][nj][3] - mn1);
                    lsum[mi][0] += p0 + p1; lsum[mi][1] += p2 + p3;
                    *(float2*)&Qs[rps * QST + kl] = make_float2(tf32r(p0), tf32r(p1));
                    *(float2*)&Qs[(rps + 8) * QST + kl] = make_float2(tf32r(p2), tf32r(p3));
                }
            }
            __syncwarp();

            // O += P V ; V loads shared across both row-groups
#pragma unroll
            for (int kf = 0; kf < 8; kf++) {
                uint32_t pa0[4], pa1[4];
                ldsm4(pa0, aQ0 + kf * 32);
                ldsm4(pa1, aQ1 + kf * 32);
                const int c0 = kf * 8 + (lane & 3);
#pragma unroll
                for (int nj = 0; nj < 8; nj++) {
                    const int n0 = nj * 8 + (lane >> 2);
                    uint32_t vb[2];
                    vb[0] = __float_as_uint(Vst[c0 * VST + n0]);
                    vb[1] = __float_as_uint(Vst[(c0 + 4) * VST + n0]);
                    mma_tf32(oc[0][nj], pa0, vb);
                    mma_tf32(oc[1][nj], pa1, vb);
                }
            }
        }
    }

    // finalize both row-groups
#pragma unroll
    for (int mi = 0; mi < 2; mi++) {
        float l0 = lsum[mi][0], l1 = lsum[mi][1];
        l0 += __shfl_xor_sync(0xffffffffu, l0, 1);
        l0 += __shfl_xor_sync(0xffffffffu, l0, 2);
        l1 += __shfl_xor_sync(0xffffffffu, l1, 1);
        l1 += __shfl_xor_sync(0xffffffffu, l1, 2);
        const float i0 = 1.f / l0, i1 = 1.f / l1;
        const int qrA = row_min + mi * 16 + (lane >> 2);
        const int qrB = qrA + 8;
#pragma unroll
        for (int nj = 0; nj < 8; nj++) {
            const int d = nj * 8 + 2 * (lane & 3);
            *(float2*)&ctx[((size_t)b * TT + qrA) * CC + h * DD + d] =
                make_float2(tf32r(oc[mi][nj][0] * i0), tf32r(oc[mi][nj][1] * i0));
            *(float2*)&ctx[((size_t)b * TT + qrB) * CC + h * DD + d] =
                make_float2(tf32r(oc[mi][nj][2] * i1), tf32r(oc[mi][nj][3] * i1));
        }
    }
}

// ---------------------------------------------------------------------------
extern "C" void kernel_launch(void* const* d_in, const int* in_sizes, int n_in,
                              void* d_out, int out_size)
{
    const float* x      = (const float*)d_in[0];
    const int*   amask  = (const int*)d_in[1];
    const float* Wqkv_w = (const float*)d_in[2];
    const float* Wqkv_b = (const float*)d_in[3];
    const float* Wo_w   = (const float*)d_in[4];
    const float* Wo_b   = (const float*)d_in[5];
    float* out = (float*)d_out;

    float *d_ctx, *d_xr, *d_wqkv, *d_wo;
    cudaGetSymbolAddress((void**)&d_ctx, g_ctx);
    cudaGetSymbolAddress((void**)&d_xr, g_xr);
    cudaGetSymbolAddress((void**)&d_wqkv, g_wqkv);
    cudaGetSymbolAddress((void**)&d_wo, g_wo);

    const int GEMM_SMEM = 4 * ASZ * 4;   // 73728 B (2 stages x 2 operands)
    cudaFuncSetAttribute(gemm_tf32<0>, cudaFuncAttributeMaxDynamicSharedMemorySize,
                         GEMM_SMEM);
    cudaFuncSetAttribute(gemm_tf32<1>, cudaFuncAttributeMaxDynamicSharedMemorySize,
                         GEMM_SMEM);
    cudaFuncSetAttribute(attn_tf32, cudaFuncAttributeMaxDynamicSharedMemorySize,
                         ATTN_SMEM);

    // 0) pre-round x / Wqkv / Wo to tf32
    {
        const int n1 = MM * CC / 4, n2 = NQKV * CC / 4, n3 = CC * CC / 4;
        round_kernel<<<(n1 + 255) / 256, 256>>>((const float4*)x, (float4*)d_xr, n1);
        round_kernel<<<(n2 + 255) / 256, 256>>>((const float4*)Wqkv_w, (float4*)d_wqkv, n2);
        round_kernel<<<(n3 + 255) / 256, 256>>>((const float4*)Wo_w, (float4*)d_wo, n3);
    }
    // 1) QKV projection -> g_qkv (tf32-rounded)
    {
        dim3 grid(NQKV / 128, MM / 128);   // (18, 32)
        gemm_tf32<1><<<grid, 256, GEMM_SMEM>>>(d_xr, d_wqkv, Wqkv_b, nullptr,
                                               MM, NQKV, CC);
    }
    // 2) attention -> g_ctx (tf32-rounded)
    {
        dim3 grid(TT / 128, BB * HH);      // (16, 24)
        attn_tf32<<<grid, 128, ATTN_SMEM>>>(amask, d_ctx);
    }
    // 3) output projection -> out (fp32)
    {
        dim3 grid(CC / 128, MM / 128);     // (6, 32)
        gemm_tf32<0><<<grid, 256, GEMM_SMEM>>>(d_ctx, d_wo, Wo_b, out, MM, CC, CC);
    }
}